// round 1
// baseline (speedup 1.0000x reference)
#include <cuda_runtime.h>
#include <math.h>

#define NG     3200   // graphs = B*L
#define E      50     // nodes per graph
#define D      100    // embedding dim
#define H      100    // head dim
#define MT     32     // graphs per CTA in GEMM kernels

// Scratch (no allocation allowed in kernel_launch)
__device__ __align__(16) float g_As[D * D];   // A^T: g_As[e*D + d] = sum_h Wk[d][h]*Wq[e][h]
__device__ __align__(16) float g_c[D];        // Wk @ bq
__device__ __align__(16) float g_bvs[H];      // bv + bs
__device__ __align__(16) float g_U[NG * D];   // per-graph u = A x0 + c
__device__ __align__(16) float g_w[NG * D];   // per-graph attention-weighted x sum

// ---------------------------------------------------------------------------
// K1: precompute A^T, c, bv+bs.  grid = D+1 blocks x 128 threads.
// block e (<D) computes row e of A^T; block D computes c and bvs.
// ---------------------------------------------------------------------------
__global__ void k_pre(const float* __restrict__ Wq, const float* __restrict__ bq,
                      const float* __restrict__ Wk,
                      const float* __restrict__ bv, const float* __restrict__ bs) {
    int e = blockIdx.x;
    int d = threadIdx.x;
    if (e < D) {
        __shared__ float wq[H];
        if (d < H) wq[d] = Wq[e * H + d];
        __syncthreads();
        if (d < D) {
            float acc = 0.f;
            #pragma unroll 4
            for (int h = 0; h < H; ++h) acc = fmaf(Wk[d * H + h], wq[h], acc);
            g_As[e * D + d] = acc;
        }
    } else {
        if (d < D) {
            float acc = 0.f;
            #pragma unroll 4
            for (int h = 0; h < H; ++h) acc = fmaf(Wk[d * H + h], bq[h], acc);
            g_c[d] = acc;
            g_bvs[d] = bv[d] + bs[d];
        }
    }
}

// ---------------------------------------------------------------------------
// K2: U[g][h] = c[h] + sum_e x0[g][e] * A^T[e][h]
// grid = NG/MT CTAs, 256 threads; A^T staged in smem once per CTA,
// 4x4 register tile per thread, float4 smem loads.
// ---------------------------------------------------------------------------
__global__ __launch_bounds__(256) void k_u(const int* __restrict__ nid,
                                           const float* __restrict__ emb) {
    extern __shared__ float sm[];
    float* As  = sm;                    // D*D
    float* x0t = sm + D * D;            // [D][MT]  (transposed x0 rows)
    float* cs  = sm + D * D + D * MT;   // D
    __shared__ int ids[MT];

    int tid   = threadIdx.x;
    int gbase = blockIdx.x * MT;

    for (int i = tid; i < D * D; i += 256) As[i] = g_As[i];
    if (tid < D)  cs[tid]  = g_c[tid];
    if (tid < MT) ids[tid] = nid[(gbase + tid) * E];
    __syncthreads();

    for (int q = tid; q < MT * (D / 4); q += 256) {
        int r = q / (D / 4), cc = q % (D / 4);
        float4 v = reinterpret_cast<const float4*>(emb)[ids[r] * (D / 4) + cc];
        x0t[(cc * 4 + 0) * MT + r] = v.x;
        x0t[(cc * 4 + 1) * MT + r] = v.y;
        x0t[(cc * 4 + 2) * MT + r] = v.z;
        x0t[(cc * 4 + 3) * MT + r] = v.w;
    }
    __syncthreads();

    if (tid < 200) {
        int ty = tid / 25, tx = tid % 25;   // 8 g-threads x 25 h-threads
        int g0 = ty * 4,   h0 = tx * 4;
        float acc[4][4];
        #pragma unroll
        for (int i = 0; i < 4; ++i)
            #pragma unroll
            for (int j = 0; j < 4; ++j) acc[i][j] = cs[h0 + j];

        #pragma unroll 2
        for (int e = 0; e < D; ++e) {
            float4 xa = *reinterpret_cast<const float4*>(&x0t[e * MT + g0]);
            float4 av = *reinterpret_cast<const float4*>(&As[e * D + h0]);
            float xs[4] = {xa.x, xa.y, xa.z, xa.w};
            float as4[4] = {av.x, av.y, av.z, av.w};
            #pragma unroll
            for (int i = 0; i < 4; ++i)
                #pragma unroll
                for (int j = 0; j < 4; ++j)
                    acc[i][j] = fmaf(xs[i], as4[j], acc[i][j]);
        }
        #pragma unroll
        for (int i = 0; i < 4; ++i) {
            int g = gbase + g0 + i;
            #pragma unroll
            for (int j = 0; j < 4; ++j) g_U[g * D + h0 + j] = acc[i][j];
        }
    }
}

// ---------------------------------------------------------------------------
// K3: per-graph attention. one CTA per graph, 128 threads.
// gather X[50][100] (pad 101) to smem; scores = X@u/10 (masked by adj[:,j,0]);
// softmax; w = attn^T X.
// ---------------------------------------------------------------------------
__global__ __launch_bounds__(128) void k_attn(const int* __restrict__ nid,
                                              const int* __restrict__ adj,
                                              const float* __restrict__ emb) {
    constexpr int LD = 101;
    __shared__ float X[E * LD];
    __shared__ float u_s[D];
    __shared__ float sc[E];
    __shared__ float ps[E];
    __shared__ int ids[E];

    int g   = blockIdx.x;
    int tid = threadIdx.x;

    if (tid < E) ids[tid] = nid[g * E + tid];
    if (tid < D) u_s[tid] = g_U[g * D + tid];
    __syncthreads();

    for (int q = tid; q < E * (D / 4); q += 128) {
        int r = q / (D / 4), cc = q % (D / 4);
        float4 v = reinterpret_cast<const float4*>(emb)[ids[r] * (D / 4) + cc];
        float* dst = &X[r * LD + cc * 4];
        dst[0] = v.x; dst[1] = v.y; dst[2] = v.z; dst[3] = v.w;
    }
    __syncthreads();

    if (tid < E) {
        const float* xr = &X[tid * LD];
        float s = 0.f;
        #pragma unroll 4
        for (int d2 = 0; d2 < D; ++d2) s = fmaf(xr[d2], u_s[d2], s);
        int m = adj[g * (E * E) + tid * E];  // adj[g][j][0] : edge j -> node 0
        sc[tid] = m ? s * 0.1f : -INFINITY;  // /sqrt(H), H=100
    }
    __syncthreads();

    float mx = -INFINITY;
    #pragma unroll
    for (int j = 0; j < E; ++j) mx = fmaxf(mx, sc[j]);
    if (tid < E) ps[tid] = expf(sc[tid] - mx);
    __syncthreads();

    float S = 0.f;
    #pragma unroll
    for (int j = 0; j < E; ++j) S += ps[j];
    float inv = 1.0f / S;  // node 0 always has self-loop -> S > 0

    if (tid < D) {
        float w = 0.f;
        #pragma unroll 2
        for (int j = 0; j < E; ++j) w = fmaf(ps[j], X[j * LD + tid], w);
        g_w[g * D + tid] = w * inv;
    }
}

// ---------------------------------------------------------------------------
// K4: out[g][h] = (bv+bs)[h] + sum_d Wv[d][h]*w[g][d] + sum_d Ws[d][h]*x0[g][d]
// concatenated K=200 GEMM, same tiling as K2.
// ---------------------------------------------------------------------------
__global__ __launch_bounds__(256) void k_out(const int* __restrict__ nid,
                                             const float* __restrict__ emb,
                                             const float* __restrict__ Wv,
                                             const float* __restrict__ Ws,
                                             float* __restrict__ out) {
    extern __shared__ float sm[];
    float* Wc  = sm;                          // [2D][H]
    float* vct = sm + 2 * D * H;              // [2D][MT]
    float* bb  = sm + 2 * D * H + 2 * D * MT; // H
    __shared__ int ids[MT];

    int tid   = threadIdx.x;
    int gbase = blockIdx.x * MT;

    for (int i = tid; i < D * H; i += 256) Wc[i] = Wv[i];
    for (int i = tid; i < D * H; i += 256) Wc[D * H + i] = Ws[i];
    if (tid < H)  bb[tid]  = g_bvs[tid];
    if (tid < MT) ids[tid] = nid[(gbase + tid) * E];
    __syncthreads();

    for (int q = tid; q < MT * (D / 4); q += 256) {
        int r = q / (D / 4), cc = q % (D / 4);
        float4 v = reinterpret_cast<const float4*>(g_w)[(gbase + r) * (D / 4) + cc];
        vct[(cc * 4 + 0) * MT + r] = v.x;
        vct[(cc * 4 + 1) * MT + r] = v.y;
        vct[(cc * 4 + 2) * MT + r] = v.z;
        vct[(cc * 4 + 3) * MT + r] = v.w;
        float4 x = reinterpret_cast<const float4*>(emb)[ids[r] * (D / 4) + cc];
        vct[(D + cc * 4 + 0) * MT + r] = x.x;
        vct[(D + cc * 4 + 1) * MT + r] = x.y;
        vct[(D + cc * 4 + 2) * MT + r] = x.z;
        vct[(D + cc * 4 + 3) * MT + r] = x.w;
    }
    __syncthreads();

    if (tid < 200) {
        int ty = tid / 25, tx = tid % 25;
        int g0 = ty * 4,   h0 = tx * 4;
        float acc[4][4];
        #pragma unroll
        for (int i = 0; i < 4; ++i)
            #pragma unroll
            for (int j = 0; j < 4; ++j) acc[i][j] = bb[h0 + j];

        #pragma unroll 2
        for (int d2 = 0; d2 < 2 * D; ++d2) {
            float4 xa = *reinterpret_cast<const float4*>(&vct[d2 * MT + g0]);
            float4 wv = *reinterpret_cast<const float4*>(&Wc[d2 * H + h0]);
            float xs[4] = {xa.x, xa.y, xa.z, xa.w};
            float ws4[4] = {wv.x, wv.y, wv.z, wv.w};
            #pragma unroll
            for (int i = 0; i < 4; ++i)
                #pragma unroll
                for (int j = 0; j < 4; ++j)
                    acc[i][j] = fmaf(xs[i], ws4[j], acc[i][j]);
        }
        #pragma unroll
        for (int i = 0; i < 4; ++i) {
            int g = gbase + g0 + i;
            #pragma unroll
            for (int j = 0; j < 4; ++j) out[g * H + h0 + j] = acc[i][j];
        }
    }
}

// ---------------------------------------------------------------------------
extern "C" void kernel_launch(void* const* d_in, const int* in_sizes, int n_in,
                              void* d_out, int out_size) {
    const int*   nid = (const int*)d_in[0];
    const int*   adj = (const int*)d_in[1];
    const float* emb = (const float*)d_in[2];
    const float* Wq  = (const float*)d_in[3];
    const float* bq  = (const float*)d_in[4];
    const float* Wk  = (const float*)d_in[5];
    // d_in[6] = bk: provably cancels in softmax (constant shift per row)
    const float* Wv  = (const float*)d_in[7];
    const float* bv  = (const float*)d_in[8];
    const float* Ws  = (const float*)d_in[9];
    const float* bs  = (const float*)d_in[10];
    float* out = (float*)d_out;

    const int smem2 = (D * D + D * MT + D) * (int)sizeof(float);           // 53.2 KB
    const int smem4 = (2 * D * H + 2 * D * MT + H) * (int)sizeof(float);   // 106 KB
    cudaFuncSetAttribute(k_u,   cudaFuncAttributeMaxDynamicSharedMemorySize, smem2);
    cudaFuncSetAttribute(k_out, cudaFuncAttributeMaxDynamicSharedMemorySize, smem4);

    k_pre<<<D + 1, 128>>>(Wq, bq, Wk, bv, bs);
    k_u<<<NG / MT, 256, smem2>>>(nid, emb);
    k_attn<<<NG, 128>>>(nid, adj, emb);
    k_out<<<NG / MT, 256, smem4>>>(nid, emb, Wv, Ws, out);
}